// round 12
// baseline (speedup 1.0000x reference)
#include <cuda_runtime.h>
#include <cstdint>

// CovNet_3058016715001 — binarized-weight MLP via int8 mma.sync.
// Round 12: round-11 barrier-free k-loop + FIX: quiesce barrier before the
// combine-buffer overlay (lo warps were clobbering hi warps' live rings).
//   h   = clip(x @ sign(W1)^T + b1, -1, 1)     x:[8192,784] W1:[4096,784]
//   out = h @ W2^T + b2                        W2:[10,4096]  out:[8192,10]
//
// 512 thr = 8 tile positions x 2 planes; each warp streams its own m32n32
// tile from a private 4x2KB smem ring with its own cp.async groups (no CTA
// barrier in the k-loop). Plane-specialized warps: 32 acc regs each.
// Combine: sync -> lo warps STS accs -> sync -> hi warps combine+fc2.

#define BATCH 8192
#define IN_F  784
#define KP8   832           // 26 * 32
#define HID   4096
#define NOUT  10

#define BM 64
#define BN 128
#define NCH 26              // k-chunks of 32

#define WSTAGE 2048         // per-warp stage: A 1KB + B 1KB
#define WRING  8192         // 4 stages
// smem map (128-aligned base):
//   [0, 131072)        16 warps x 8KB rings (reused as combine buffers)
//   [131072, 136192)   W2s [10][128] f32
//   [136192, 136704)   b1s [128] f32
#define OFF_W2   131072
#define OFF_B1   136192
#define SMEM_REQ (136704 + 128)

#define SCALE_S 4096.0f
#define INV_S   (1.0f / 4096.0f)

static __device__ char g_Xh8[(size_t)BATCH * KP8];
static __device__ char g_Xl8[(size_t)BATCH * KP8];
static __device__ char g_W8 [(size_t)HID * KP8];

// ---------------------------------------------------------------- helpers
__device__ __forceinline__ uint32_t smem_u32(const void* p) {
    return (uint32_t)__cvta_generic_to_shared(p);
}

#define CP_ASYNC16(s, g) \
    asm volatile("cp.async.cg.shared.global [%0], [%1], 16;" :: "r"(s), "l"(g))
#define CP_COMMIT() asm volatile("cp.async.commit_group;")
#define CP_WAIT(n)  asm volatile("cp.async.wait_group %0;" :: "n"(n) : "memory")

__device__ __forceinline__ void ldm_x4(uint32_t& r0, uint32_t& r1, uint32_t& r2,
                                       uint32_t& r3, uint32_t addr) {
    asm volatile("ldmatrix.sync.aligned.m8n8.x4.shared.b16 {%0,%1,%2,%3}, [%4];"
                 : "=r"(r0), "=r"(r1), "=r"(r2), "=r"(r3) : "r"(addr));
}

#define MMA_S8(d, a, b) \
    asm volatile("mma.sync.aligned.m16n8k32.row.col.s32.s8.s8.s32 " \
        "{%0,%1,%2,%3}, {%4,%5,%6,%7}, {%8,%9}, {%0,%1,%2,%3};" \
        : "+r"((d)[0]), "+r"((d)[1]), "+r"((d)[2]), "+r"((d)[3]) \
        : "r"((a)[0]), "r"((a)[1]), "r"((a)[2]), "r"((a)[3]), \
          "r"((b)[0]), "r"((b)[1]))

__device__ __forceinline__ uint32_t sw128(uint32_t flat) {
    return flat ^ ((flat >> 3) & 0x70);
}

// ---------------------------------------------------------------- prep
__global__ void init_out_kernel(float* __restrict__ out, const float* __restrict__ b2) {
    int i = blockIdx.x * blockDim.x + threadIdx.x;
    if (i < BATCH * NOUT) out[i] = b2[i % NOUT];
}

__global__ void conv_x8_kernel(const float* __restrict__ X) {
    int idx = blockIdx.x * blockDim.x + threadIdx.x;
    if (idx >= BATCH * (KP8 / 4)) return;
    int r  = idx / (KP8 / 4);
    int c4 = (idx % (KP8 / 4)) * 4;
    char hq[4], lq[4];
    #pragma unroll
    for (int j = 0; j < 4; ++j) {
        int col = c4 + j;
        float x = (col < IN_F) ? X[(size_t)r * IN_F + col] : 0.0f;
        int Q = __float2int_rn(x * SCALE_S);
        Q = max(-32512, min(32512, Q));
        int Qh = (Q + 128) >> 8;
        int Ql = Q - (Qh << 8);
        hq[j] = (char)Qh;
        lq[j] = (char)Ql;
    }
    *(char4*)(g_Xh8 + (size_t)r * KP8 + c4) = make_char4(hq[0], hq[1], hq[2], hq[3]);
    *(char4*)(g_Xl8 + (size_t)r * KP8 + c4) = make_char4(lq[0], lq[1], lq[2], lq[3]);
}

__global__ void conv_w8_kernel(const float* __restrict__ W1) {
    int idx = blockIdx.x * blockDim.x + threadIdx.x;
    if (idx >= HID * (KP8 / 4)) return;
    int r  = idx / (KP8 / 4);
    int c4 = (idx % (KP8 / 4)) * 4;
    char s[4];
    #pragma unroll
    for (int j = 0; j < 4; ++j) {
        int col = c4 + j;
        char v = 0;
        if (col < IN_F) {
            float w = W1[(size_t)r * IN_F + col];
            v = (w > 0.0f) ? (char)1 : ((w < 0.0f) ? (char)-1 : (char)0);
        }
        s[j] = v;
    }
    *(char4*)(g_W8 + (size_t)r * KP8 + c4) = make_char4(s[0], s[1], s[2], s[3]);
}

// ---------------------------------------------------------------- main
__global__ void __launch_bounds__(512, 1) fused_i8_kernel(
    const float* __restrict__ b1, const float* __restrict__ W2,
    float* __restrict__ out)
{
    extern __shared__ char smem_raw[];
    const uint32_t rawA  = smem_u32(smem_raw);
    const uint32_t sbase = (rawA + 127) & ~127u;
    char* gbase = smem_raw + (sbase - rawA);
    float* W2s = (float*)(gbase + OFF_W2);
    float* b1s = (float*)(gbase + OFF_B1);

    const int tid   = threadIdx.x;
    const int lane  = tid & 31;
    const int wid   = tid >> 5;
    const int plane = wid & 1;        // 0 = hi, 1 = lo
    const int pos   = wid >> 1;       // 0..7 tile positions
    const int wm    = pos & 1;        // 2 along M (32 rows)
    const int wn    = pos >> 1;       // 4 along N (32 cols)

    const int bm = blockIdx.y * BM;
    const int bn = blockIdx.x * BN;

    // ---- stage W2 / b1 (read only after the quiesce barrier) ----
    for (int i = tid; i < NOUT * BN; i += 512)
        W2s[i] = W2[(size_t)(i >> 7) * HID + bn + (i & 127)];
    if (tid < BN) b1s[tid] = b1[bn + tid];

    // ---- per-warp private ring ----
    const uint32_t wbase = sbase + (uint32_t)wid * WRING;

    // loader: lane = row; two 16B segs per row
    const uint32_t aSw0 = sw128((uint32_t)lane * 32);
    const uint32_t aSw1 = sw128((uint32_t)lane * 32 + 16);
    const char* gA = (plane ? g_Xl8 : g_Xh8)
                     + (size_t)(bm + wm * 32 + lane) * KP8;
    const char* gB = g_W8 + (size_t)(bn + wn * 32 + lane) * KP8;

    // ldmatrix per-lane offsets within private 1KB tiles (32B rows)
    const int lg  = lane >> 3;
    const int lr8 = lane & 7;
    uint32_t aOff[2], bOff[2];
    #pragma unroll
    for (int mi = 0; mi < 2; ++mi)
        aOff[mi] = sw128((uint32_t)((mi * 16 + ((lg & 1) << 3) + lr8) * 32
                                    + (lg >> 1) * 16));
    #pragma unroll
    for (int n2 = 0; n2 < 2; ++n2)
        bOff[n2] = sw128((uint32_t)((n2 * 16 + (((lane >> 4) & 1) << 3) + lr8) * 32
                                    + (lg & 1) * 16));

    int acc[2][4][4];                 // [mi][ni][4] — one plane only
    #pragma unroll
    for (int mi = 0; mi < 2; ++mi)
        #pragma unroll
        for (int ni = 0; ni < 4; ++ni)
            #pragma unroll
            for (int q = 0; q < 4; ++q) acc[mi][ni][q] = 0;

    #define LOAD_CHUNK(c) do {                                    \
        uint32_t stg_ = wbase + (uint32_t)((c) & 3) * WSTAGE;     \
        CP_ASYNC16(stg_ + aSw0,        gA + (c) * 32);            \
        CP_ASYNC16(stg_ + aSw1,        gA + (c) * 32 + 16);       \
        CP_ASYNC16(stg_ + 1024 + aSw0, gB + (c) * 32);            \
        CP_ASYNC16(stg_ + 1024 + aSw1, gB + (c) * 32 + 16);       \
    } while (0)

    // preload chunks 0..2 (one group each)
    LOAD_CHUNK(0); CP_COMMIT();
    LOAD_CHUNK(1); CP_COMMIT();
    LOAD_CHUNK(2); CP_COMMIT();

    // ---- barrier-free main loop: each warp runs its own pipeline ----
    for (int kc = 0; kc < NCH; ++kc) {
        if (kc + 3 < NCH) LOAD_CHUNK(kc + 3);
        CP_COMMIT();                   // committed even when empty: keeps
        CP_WAIT(3);                    // group accounting exact at the tail

        const uint32_t base = wbase + (uint32_t)(kc & 3) * WSTAGE;

        uint32_t bb[4][2], aa[2][4];
        #pragma unroll
        for (int n2 = 0; n2 < 2; ++n2)
            ldm_x4(bb[2 * n2][0], bb[2 * n2][1], bb[2 * n2 + 1][0],
                   bb[2 * n2 + 1][1], base + 1024 + bOff[n2]);
        #pragma unroll
        for (int mi = 0; mi < 2; ++mi)
            ldm_x4(aa[mi][0], aa[mi][1], aa[mi][2], aa[mi][3], base + aOff[mi]);

        #pragma unroll
        for (int mi = 0; mi < 2; ++mi)
            #pragma unroll
            for (int ni = 0; ni < 4; ++ni)
                MMA_S8(acc[mi][ni], aa[mi], bb[ni]);
    }
    #undef LOAD_CHUNK

    // ---- FIX: quiesce all warps' rings BEFORE overlaying combine buffers ----
    __syncthreads();

    // combine buffer overlays the now-dead stage rings: pos * 4KB
    const uint32_t cb = sbase + (uint32_t)pos * 4096;

    if (plane == 1) {
        #pragma unroll
        for (int mi = 0; mi < 2; ++mi)
            #pragma unroll
            for (int ni = 0; ni < 4; ++ni) {
                uint32_t addr = cb + (uint32_t)(((mi * 4 + ni) * 32 + lane) * 16);
                asm volatile("st.shared.v4.b32 [%0], {%1,%2,%3,%4};"
                             :: "r"(addr), "r"((uint32_t)acc[mi][ni][0]),
                                "r"((uint32_t)acc[mi][ni][1]),
                                "r"((uint32_t)acc[mi][ni][2]),
                                "r"((uint32_t)acc[mi][ni][3]) : "memory");
            }
    }
    __syncthreads();

    if (plane == 0) {
        const int dg = lane >> 2;
        const int dt = lane & 3;

        float hv[2][4][4];
        #pragma unroll
        for (int mi = 0; mi < 2; ++mi)
            #pragma unroll
            for (int ni = 0; ni < 4; ++ni) {
                uint32_t lo0, lo1, lo2, lo3;
                uint32_t addr = cb + (uint32_t)(((mi * 4 + ni) * 32 + lane) * 16);
                asm volatile("ld.shared.v4.b32 {%0,%1,%2,%3}, [%4];"
                             : "=r"(lo0), "=r"(lo1), "=r"(lo2), "=r"(lo3)
                             : "r"(addr));
                int aL[4] = {(int)lo0, (int)lo1, (int)lo2, (int)lo3};
                #pragma unroll
                for (int q = 0; q < 4; ++q) {
                    int n = wn * 32 + ni * 8 + 2 * dt + (q & 1);
                    float hf = fmaf(256.0f, (float)acc[mi][ni][q], (float)aL[q]);
                    float v  = fmaf(hf, INV_S, b1s[n]);
                    hv[mi][ni][q] = fminf(1.0f, fmaxf(-1.0f, v));
                }
            }

        #pragma unroll
        for (int o = 0; o < NOUT; ++o) {
            #pragma unroll
            for (int mi = 0; mi < 2; ++mi) {
                float s0 = 0.0f, s1 = 0.0f;
                #pragma unroll
                for (int ni = 0; ni < 4; ++ni) {
                    int n0 = wn * 32 + ni * 8 + 2 * dt;
                    float w0 = W2s[o * BN + n0];
                    float w1 = W2s[o * BN + n0 + 1];
                    s0 = fmaf(hv[mi][ni][0], w0, fmaf(hv[mi][ni][1], w1, s0));
                    s1 = fmaf(hv[mi][ni][2], w0, fmaf(hv[mi][ni][3], w1, s1));
                }
                s0 += __shfl_xor_sync(0xffffffffu, s0, 1);
                s0 += __shfl_xor_sync(0xffffffffu, s0, 2);
                s1 += __shfl_xor_sync(0xffffffffu, s1, 1);
                s1 += __shfl_xor_sync(0xffffffffu, s1, 2);
                if (dt == 0) {
                    int r0 = bm + wm * 32 + mi * 16 + dg;
                    atomicAdd(&out[(size_t)r0 * NOUT + o], s0);
                    atomicAdd(&out[(size_t)(r0 + 8) * NOUT + o], s1);
                }
            }
        }
    }
}

// ---------------------------------------------------------------- launch
extern "C" void kernel_launch(void* const* d_in, const int* in_sizes, int n_in,
                              void* d_out, int out_size) {
    const float* X  = (const float*)d_in[0];   // [8192, 784]
    const float* W1 = (const float*)d_in[1];   // [4096, 784]
    const float* b1 = (const float*)d_in[2];   // [4096]
    const float* W2 = (const float*)d_in[3];   // [10, 4096]
    const float* b2 = (const float*)d_in[4];   // [10]
    float* out = (float*)d_out;                // [8192, 10]
    (void)in_sizes; (void)n_in; (void)out_size;

    cudaFuncSetAttribute(fused_i8_kernel,
                         cudaFuncAttributeMaxDynamicSharedMemorySize, SMEM_REQ);

    init_out_kernel<<<(BATCH * NOUT + 255) / 256, 256>>>(out, b2);
    conv_x8_kernel<<<(BATCH * (KP8 / 4) + 255) / 256, 256>>>(X);
    conv_w8_kernel<<<(HID * (KP8 / 4) + 255) / 256, 256>>>(W1);

    dim3 grid(HID / BN, BATCH / BM);   // (32, 128) = 4096 CTAs
    fused_i8_kernel<<<grid, 512, SMEM_REQ>>>(b1, W2, out);
}

// round 13
// speedup vs baseline: 3.6001x; 3.6001x over previous
#include <cuda_runtime.h>
#include <cstdint>

// CovNet_3058016715001 — binarized-weight MLP via int8 dual-plane mma.sync.
// Round 13: round-7 warp (m32n32, BK=64) kept intact, but 4-warp 128-thread
// CTAs at 4 CTAs/SM -> 4 independent barrier domains per SM. Each SMSP gets
// one warp from each CTA, so per-CTA LDSM/wait convoys decorrelate and fill
// the tensor pipe.
//   h   = clip(x @ sign(W1)^T + b1, -1, 1)     x:[8192,784] W1:[4096,784]
//   out = h @ W2^T + b2                        W2:[10,4096]  out:[8192,10]
//
// x -> Q = round(x*4096) = 256*Qh + Ql (two s8 planes); sign(W1) exact s8.
// Dual s32 accumulators; epilogue h = (256*accH + accL)/4096 + b1 -> clip
// -> fused fc2 -> atomicAdd (out pre-seeded with b2).

#define BATCH 8192
#define IN_F  784
#define KP8   832           // 13 * 64
#define HID   4096
#define NOUT  10

#define BM 64
#define BN 64
#define BK 64
#define NCH 13
#define NSTG 4

// stage layout: A_hi [64x64]=4K | A_lo 4K | B [64x64]=4K
#define OFF_ALO 4096
#define OFF_BW  8192
#define STAGE   12288

// dynamic smem map (128-aligned base):
//   [0, 49152)       4 stages
//   [49152, 51712)   W2s [10][64] f32
//   [51712, 51968)   b1s [64] f32
#define OFF_W2   49152
#define OFF_B1   51712
#define SMEM_REQ (51968 + 128)

#define SCALE_S 4096.0f
#define INV_S   (1.0f / 4096.0f)

static __device__ char g_Xh8[(size_t)BATCH * KP8];
static __device__ char g_Xl8[(size_t)BATCH * KP8];
static __device__ char g_W8 [(size_t)HID * KP8];

// ---------------------------------------------------------------- helpers
__device__ __forceinline__ uint32_t smem_u32(const void* p) {
    return (uint32_t)__cvta_generic_to_shared(p);
}

#define CP_ASYNC16(s, g) \
    asm volatile("cp.async.cg.shared.global [%0], [%1], 16;" :: "r"(s), "l"(g))
#define CP_COMMIT() asm volatile("cp.async.commit_group;")
#define CP_WAIT(n)  asm volatile("cp.async.wait_group %0;" :: "n"(n) : "memory")

__device__ __forceinline__ void ldm_x4(uint32_t& r0, uint32_t& r1, uint32_t& r2,
                                       uint32_t& r3, uint32_t addr) {
    asm volatile("ldmatrix.sync.aligned.m8n8.x4.shared.b16 {%0,%1,%2,%3}, [%4];"
                 : "=r"(r0), "=r"(r1), "=r"(r2), "=r"(r3) : "r"(addr));
}

#define MMA_S8(d, a, b) \
    asm volatile("mma.sync.aligned.m16n8k32.row.col.s32.s8.s8.s32 " \
        "{%0,%1,%2,%3}, {%4,%5,%6,%7}, {%8,%9}, {%0,%1,%2,%3};" \
        : "+r"((d)[0]), "+r"((d)[1]), "+r"((d)[2]), "+r"((d)[3]) \
        : "r"((a)[0]), "r"((a)[1]), "r"((a)[2]), "r"((a)[3]), \
          "r"((b)[0]), "r"((b)[1]))

__device__ __forceinline__ uint32_t sw128(uint32_t flat) {
    return flat ^ ((flat >> 3) & 0x70);
}

// ---------------------------------------------------------------- prep
__global__ void init_out_kernel(float* __restrict__ out, const float* __restrict__ b2) {
    int i = blockIdx.x * blockDim.x + threadIdx.x;
    if (i < BATCH * NOUT) out[i] = b2[i % NOUT];
}

__global__ void conv_x8_kernel(const float* __restrict__ X) {
    int idx = blockIdx.x * blockDim.x + threadIdx.x;
    if (idx >= BATCH * (KP8 / 4)) return;
    int r  = idx / (KP8 / 4);
    int c4 = (idx % (KP8 / 4)) * 4;
    char hq[4], lq[4];
    #pragma unroll
    for (int j = 0; j < 4; ++j) {
        int col = c4 + j;
        float x = (col < IN_F) ? X[(size_t)r * IN_F + col] : 0.0f;
        int Q = __float2int_rn(x * SCALE_S);
        Q = max(-32512, min(32512, Q));
        int Qh = (Q + 128) >> 8;
        int Ql = Q - (Qh << 8);
        hq[j] = (char)Qh;
        lq[j] = (char)Ql;
    }
    *(char4*)(g_Xh8 + (size_t)r * KP8 + c4) = make_char4(hq[0], hq[1], hq[2], hq[3]);
    *(char4*)(g_Xl8 + (size_t)r * KP8 + c4) = make_char4(lq[0], lq[1], lq[2], lq[3]);
}

__global__ void conv_w8_kernel(const float* __restrict__ W1) {
    int idx = blockIdx.x * blockDim.x + threadIdx.x;
    if (idx >= HID * (KP8 / 4)) return;
    int r  = idx / (KP8 / 4);
    int c4 = (idx % (KP8 / 4)) * 4;
    char s[4];
    #pragma unroll
    for (int j = 0; j < 4; ++j) {
        int col = c4 + j;
        char v = 0;
        if (col < IN_F) {
            float w = W1[(size_t)r * IN_F + col];
            v = (w > 0.0f) ? (char)1 : ((w < 0.0f) ? (char)-1 : (char)0);
        }
        s[j] = v;
    }
    *(char4*)(g_W8 + (size_t)r * KP8 + c4) = make_char4(s[0], s[1], s[2], s[3]);
}

// ---------------------------------------------------------------- main
__global__ void __launch_bounds__(128, 4) fused_i8_kernel(
    const float* __restrict__ b1, const float* __restrict__ W2,
    float* __restrict__ out)
{
    extern __shared__ char smem_raw[];
    const uint32_t rawA  = smem_u32(smem_raw);
    const uint32_t sbase = (rawA + 127) & ~127u;
    char* gbase = smem_raw + (sbase - rawA);
    float* W2s = (float*)(gbase + OFF_W2);   // [10][64]
    float* b1s = (float*)(gbase + OFF_B1);   // [64]

    const int tid  = threadIdx.x;
    const int lane = tid & 31;
    const int wid  = tid >> 5;       // 0..3
    const int wm   = wid & 1;        // 2 warps along M (32 rows each)
    const int wn   = wid >> 1;       // 2 warps along N (32 cols each)

    const int bm = blockIdx.y * BM;
    const int bn = blockIdx.x * BN;

    // ---- stage W2 / b1 slices (used only in epilogue) ----
    for (int i = tid; i < NOUT * BN; i += 128)
        W2s[i] = W2[(size_t)(i >> 6) * HID + bn + (i & 63)];
    if (tid < BN) b1s[tid] = b1[bn + tid];

    // ---- loader mapping: per tile, 256 x 16B chunks; 2 per thread ----
    // chunk cid = it*128 + tid; row = cid>>2; seg = cid&3; flat = cid*16
    uint32_t sSw[2];
    const char* pXh[2];
    const char* pXl[2];
    const char* pW [2];
    #pragma unroll
    for (int it = 0; it < 2; ++it) {
        int cid = it * 128 + tid;
        int row = cid >> 2;
        int seg = cid & 3;
        sSw[it] = sw128((uint32_t)cid * 16);
        pXh[it] = g_Xh8 + (size_t)(bm + row) * KP8 + seg * 16;
        pXl[it] = g_Xl8 + (size_t)(bm + row) * KP8 + seg * 16;
        pW [it] = g_W8  + (size_t)(bn + row) * KP8 + seg * 16;
    }

    // ---- ldmatrix per-lane offsets (row stride 64 B, 2 k-steps) ----
    const int lg  = lane >> 3;
    const int lr8 = lane & 7;
    uint32_t aOff[2][2], bOff[2][2];
    #pragma unroll
    for (int mi = 0; mi < 2; ++mi) {
        int r = wm * 32 + mi * 16 + ((lg & 1) << 3) + lr8;
        #pragma unroll
        for (int ks = 0; ks < 2; ++ks)
            aOff[mi][ks] = sw128((uint32_t)(r * 64 + ks * 32 + (lg >> 1) * 16));
    }
    #pragma unroll
    for (int n2 = 0; n2 < 2; ++n2) {
        int r = wn * 32 + n2 * 16 + (((lane >> 4) & 1) << 3) + lr8;
        #pragma unroll
        for (int ks = 0; ks < 2; ++ks)
            bOff[n2][ks] = sw128((uint32_t)(r * 64 + ks * 32 + (lg & 1) * 16));
    }

    int accH[2][4][4], accL[2][4][4];
    #pragma unroll
    for (int mi = 0; mi < 2; ++mi)
        #pragma unroll
        for (int ni = 0; ni < 4; ++ni)
            #pragma unroll
            for (int q = 0; q < 4; ++q) { accH[mi][ni][q] = 0; accL[mi][ni][q] = 0; }

    #define LOAD_CHUNK(c) do {                                              \
        uint32_t dst_ = sbase + (uint32_t)((c) & 3) * STAGE;                \
        _Pragma("unroll")                                                   \
        for (int it = 0; it < 2; ++it) {                                    \
            CP_ASYNC16(dst_ + sSw[it],            pXh[it] + (c) * BK);      \
            CP_ASYNC16(dst_ + OFF_ALO + sSw[it],  pXl[it] + (c) * BK);      \
            CP_ASYNC16(dst_ + OFF_BW  + sSw[it],  pW [it] + (c) * BK);      \
        }                                                                   \
        CP_COMMIT();                                                        \
    } while (0)

    // ---- preload chunks 0..2 ----
    LOAD_CHUNK(0);
    LOAD_CHUNK(1);
    LOAD_CHUNK(2);

    for (int kc = 0; kc < NCH; ++kc) {
        const int s = kc & 3;
        if (kc < NCH - 2)       { CP_WAIT(2); }
        else if (kc == NCH - 2) { CP_WAIT(1); }
        else                    { CP_WAIT(0); }
        __syncthreads();

        if (kc + 3 < NCH) LOAD_CHUNK(kc + 3);

        const uint32_t base = sbase + s * STAGE;
        #pragma unroll
        for (int ks = 0; ks < 2; ++ks) {
            uint32_t ah[2][4], al[2][4], bb[4][2];
            #pragma unroll
            for (int n2 = 0; n2 < 2; ++n2)
                ldm_x4(bb[2 * n2][0], bb[2 * n2][1], bb[2 * n2 + 1][0],
                       bb[2 * n2 + 1][1], base + OFF_BW + bOff[n2][ks]);
            #pragma unroll
            for (int mi = 0; mi < 2; ++mi)
                ldm_x4(ah[mi][0], ah[mi][1], ah[mi][2], ah[mi][3],
                       base + aOff[mi][ks]);
            #pragma unroll
            for (int mi = 0; mi < 2; ++mi)
                ldm_x4(al[mi][0], al[mi][1], al[mi][2], al[mi][3],
                       base + OFF_ALO + aOff[mi][ks]);

            #pragma unroll
            for (int mi = 0; mi < 2; ++mi)
                #pragma unroll
                for (int ni = 0; ni < 4; ++ni) {
                    MMA_S8(accH[mi][ni], ah[mi], bb[ni]);
                    MMA_S8(accL[mi][ni], al[mi], bb[ni]);
                }
        }
    }
    #undef LOAD_CHUNK

    // ---- epilogue: combine planes, bias + hardtanh, fused fc2 ----
    const int dg = lane >> 2;
    const int dt = lane & 3;

    float hv[2][4][4];
    #pragma unroll
    for (int mi = 0; mi < 2; ++mi)
        #pragma unroll
        for (int ni = 0; ni < 4; ++ni)
            #pragma unroll
            for (int q = 0; q < 4; ++q) {
                int n = wn * 32 + ni * 8 + 2 * dt + (q & 1);
                float hf = fmaf(256.0f, (float)accH[mi][ni][q], (float)accL[mi][ni][q]);
                float v  = fmaf(hf, INV_S, b1s[n]);
                hv[mi][ni][q] = fminf(1.0f, fmaxf(-1.0f, v));
            }

    #pragma unroll
    for (int o = 0; o < NOUT; ++o) {
        #pragma unroll
        for (int mi = 0; mi < 2; ++mi) {
            float s0 = 0.0f, s1 = 0.0f;
            #pragma unroll
            for (int ni = 0; ni < 4; ++ni) {
                int n0 = wn * 32 + ni * 8 + 2 * dt;
                float w0 = W2s[o * BN + n0];
                float w1 = W2s[o * BN + n0 + 1];
                s0 = fmaf(hv[mi][ni][0], w0, fmaf(hv[mi][ni][1], w1, s0));
                s1 = fmaf(hv[mi][ni][2], w0, fmaf(hv[mi][ni][3], w1, s1));
            }
            s0 += __shfl_xor_sync(0xffffffffu, s0, 1);
            s0 += __shfl_xor_sync(0xffffffffu, s0, 2);
            s1 += __shfl_xor_sync(0xffffffffu, s1, 1);
            s1 += __shfl_xor_sync(0xffffffffu, s1, 2);
            if (dt == 0) {
                int r0 = bm + wm * 32 + mi * 16 + dg;
                atomicAdd(&out[(size_t)r0 * NOUT + o], s0);
                atomicAdd(&out[(size_t)(r0 + 8) * NOUT + o], s1);
            }
        }
    }
}

// ---------------------------------------------------------------- launch
extern "C" void kernel_launch(void* const* d_in, const int* in_sizes, int n_in,
                              void* d_out, int out_size) {
    const float* X  = (const float*)d_in[0];   // [8192, 784]
    const float* W1 = (const float*)d_in[1];   // [4096, 784]
    const float* b1 = (const float*)d_in[2];   // [4096]
    const float* W2 = (const float*)d_in[3];   // [10, 4096]
    const float* b2 = (const float*)d_in[4];   // [10]
    float* out = (float*)d_out;                // [8192, 10]
    (void)in_sizes; (void)n_in; (void)out_size;

    cudaFuncSetAttribute(fused_i8_kernel,
                         cudaFuncAttributeMaxDynamicSharedMemorySize, SMEM_REQ);

    init_out_kernel<<<(BATCH * NOUT + 255) / 256, 256>>>(out, b2);
    conv_x8_kernel<<<(BATCH * (KP8 / 4) + 255) / 256, 256>>>(X);
    conv_w8_kernel<<<(HID * (KP8 / 4) + 255) / 256, 256>>>(W1);

    dim3 grid(HID / BN, BATCH / BM);   // (64, 128) = 8192 CTAs
    fused_i8_kernel<<<grid, 128, SMEM_REQ>>>(b1, W2, out);
}

// round 14
// speedup vs baseline: 3.9458x; 1.0960x over previous
#include <cuda_runtime.h>
#include <cstdint>

// CovNet_3058016715001 — binarized-weight MLP via int8 mma.sync.
// Round 14: round-2's warp shape (m32xN64, unified acc) ported to s8 via
// plane-specialized warps. CTA 128x128, 512 thr = 8 positions x 2 planes,
// BK=64, 3-stage pipeline. Planes combined in smem after a quiesce barrier.
//   h   = clip(x @ sign(W1)^T + b1, -1, 1)     x:[8192,784] W1:[4096,784]
//   out = h @ W2^T + b2                        W2:[10,4096]  out:[8192,10]
//
// x -> Q = round(x*4096) = 256*Qh + Ql (two s8 planes); sign(W1) exact s8.
// h = (256*accH + accL)/4096 + b1 -> clip -> fused fc2 -> atomicAdd.

#define BATCH 8192
#define IN_F  784
#define KP8   832           // 13 * 64
#define HID   4096
#define NOUT  10

#define BM 128
#define BN 128
#define BK 64
#define NCH 13

// stage: A_hi [128x64]=8K | A_lo 8K | B [128x64]=8K
#define OFF_ALO 8192
#define OFF_BW  16384
#define STAGE   24576       // x3 stages = 73728

#define OFF_W2   73728      // [10][128] f32 = 5120
#define OFF_B1   78848      // [128] f32 = 512
#define SMEM_REQ (79360 + 128)

#define SCALE_S 4096.0f
#define INV_S   (1.0f / 4096.0f)

static __device__ char g_Xh8[(size_t)BATCH * KP8];
static __device__ char g_Xl8[(size_t)BATCH * KP8];
static __device__ char g_W8 [(size_t)HID * KP8];

// ---------------------------------------------------------------- helpers
__device__ __forceinline__ uint32_t smem_u32(const void* p) {
    return (uint32_t)__cvta_generic_to_shared(p);
}

#define CP_ASYNC16(s, g) \
    asm volatile("cp.async.cg.shared.global [%0], [%1], 16;" :: "r"(s), "l"(g))
#define CP_COMMIT() asm volatile("cp.async.commit_group;")
#define CP_WAIT(n)  asm volatile("cp.async.wait_group %0;" :: "n"(n) : "memory")

__device__ __forceinline__ void ldm_x4(uint32_t& r0, uint32_t& r1, uint32_t& r2,
                                       uint32_t& r3, uint32_t addr) {
    asm volatile("ldmatrix.sync.aligned.m8n8.x4.shared.b16 {%0,%1,%2,%3}, [%4];"
                 : "=r"(r0), "=r"(r1), "=r"(r2), "=r"(r3) : "r"(addr));
}

#define MMA_S8(d, a, b) \
    asm volatile("mma.sync.aligned.m16n8k32.row.col.s32.s8.s8.s32 " \
        "{%0,%1,%2,%3}, {%4,%5,%6,%7}, {%8,%9}, {%0,%1,%2,%3};" \
        : "+r"((d)[0]), "+r"((d)[1]), "+r"((d)[2]), "+r"((d)[3]) \
        : "r"((a)[0]), "r"((a)[1]), "r"((a)[2]), "r"((a)[3]), \
          "r"((b)[0]), "r"((b)[1]))

__device__ __forceinline__ uint32_t sw128(uint32_t flat) {
    return flat ^ ((flat >> 3) & 0x70);
}

// ---------------------------------------------------------------- prep
__global__ void init_out_kernel(float* __restrict__ out, const float* __restrict__ b2) {
    int i = blockIdx.x * blockDim.x + threadIdx.x;
    if (i < BATCH * NOUT) out[i] = b2[i % NOUT];
}

__global__ void conv_x8_kernel(const float* __restrict__ X) {
    int idx = blockIdx.x * blockDim.x + threadIdx.x;
    if (idx >= BATCH * (KP8 / 4)) return;
    int r  = idx / (KP8 / 4);
    int c4 = (idx % (KP8 / 4)) * 4;
    char hq[4], lq[4];
    #pragma unroll
    for (int j = 0; j < 4; ++j) {
        int col = c4 + j;
        float x = (col < IN_F) ? X[(size_t)r * IN_F + col] : 0.0f;
        int Q = __float2int_rn(x * SCALE_S);
        Q = max(-32512, min(32512, Q));
        int Qh = (Q + 128) >> 8;
        int Ql = Q - (Qh << 8);
        hq[j] = (char)Qh;
        lq[j] = (char)Ql;
    }
    *(char4*)(g_Xh8 + (size_t)r * KP8 + c4) = make_char4(hq[0], hq[1], hq[2], hq[3]);
    *(char4*)(g_Xl8 + (size_t)r * KP8 + c4) = make_char4(lq[0], lq[1], lq[2], lq[3]);
}

__global__ void conv_w8_kernel(const float* __restrict__ W1) {
    int idx = blockIdx.x * blockDim.x + threadIdx.x;
    if (idx >= HID * (KP8 / 4)) return;
    int r  = idx / (KP8 / 4);
    int c4 = (idx % (KP8 / 4)) * 4;
    char s[4];
    #pragma unroll
    for (int j = 0; j < 4; ++j) {
        int col = c4 + j;
        char v = 0;
        if (col < IN_F) {
            float w = W1[(size_t)r * IN_F + col];
            v = (w > 0.0f) ? (char)1 : ((w < 0.0f) ? (char)-1 : (char)0);
        }
        s[j] = v;
    }
    *(char4*)(g_W8 + (size_t)r * KP8 + c4) = make_char4(s[0], s[1], s[2], s[3]);
}

// ---------------------------------------------------------------- main
__global__ void __launch_bounds__(512, 1) fused_i8_kernel(
    const float* __restrict__ b1, const float* __restrict__ W2,
    float* __restrict__ out)
{
    extern __shared__ char smem_raw[];
    const uint32_t rawA  = smem_u32(smem_raw);
    const uint32_t sbase = (rawA + 127) & ~127u;
    char* gbase = smem_raw + (sbase - rawA);
    float* W2s = (float*)(gbase + OFF_W2);   // [10][128]
    float* b1s = (float*)(gbase + OFF_B1);   // [128]

    const int tid   = threadIdx.x;
    const int lane  = tid & 31;
    const int wid   = tid >> 5;
    const int plane = wid & 1;        // 0 = hi, 1 = lo
    const int pos   = wid >> 1;       // 0..7
    const int wm    = pos & 3;        // 4 m-positions (32 rows each)
    const int wnn   = pos >> 2;       // 2 n-positions (64 cols each)

    const int bm = blockIdx.y * BM;
    const int bn = blockIdx.x * BN;

    // ---- stage W2 / b1 slices (epilogue only) ----
    for (int i = tid; i < NOUT * BN; i += 512)
        W2s[i] = W2[(size_t)(i >> 7) * HID + bn + (i & 127)];
    if (tid < BN) b1s[tid] = b1[bn + tid];

    // ---- loader: 512 threads, 3 x 16B each (one per tile) ----
    const int lrow = tid >> 2;           // 0..127
    const int lseg = tid & 3;
    const uint32_t sSw = sw128((uint32_t)tid * 16);
    const char* gXh = g_Xh8 + (size_t)(bm + lrow) * KP8 + lseg * 16;
    const char* gXl = g_Xl8 + (size_t)(bm + lrow) * KP8 + lseg * 16;
    const char* gW  = g_W8  + (size_t)(bn + lrow) * KP8 + lseg * 16;

    // ---- ldmatrix offsets (64B rows, 2 k-steps) ----
    const int lg  = lane >> 3;
    const int lr8 = lane & 7;
    uint32_t aOff[2][2], bOff[4][2];
    #pragma unroll
    for (int mi = 0; mi < 2; ++mi) {
        int r = wm * 32 + mi * 16 + ((lg & 1) << 3) + lr8;
        #pragma unroll
        for (int ks = 0; ks < 2; ++ks)
            aOff[mi][ks] = sw128((uint32_t)(r * 64 + ks * 32 + (lg >> 1) * 16));
    }
    #pragma unroll
    for (int n2 = 0; n2 < 4; ++n2) {
        int r = wnn * 64 + n2 * 16 + (((lane >> 4) & 1) << 3) + lr8;
        #pragma unroll
        for (int ks = 0; ks < 2; ++ks)
            bOff[n2][ks] = sw128((uint32_t)(r * 64 + ks * 32 + (lg & 1) * 16));
    }

    // this warp's A plane offset within a stage
    const uint32_t aPl = plane ? (uint32_t)OFF_ALO : 0u;

    int acc[2][8][4];                 // 64 regs — single plane, n64
    #pragma unroll
    for (int mi = 0; mi < 2; ++mi)
        #pragma unroll
        for (int ni = 0; ni < 8; ++ni)
            #pragma unroll
            for (int q = 0; q < 4; ++q) acc[mi][ni][q] = 0;

    #define LOAD_CHUNK(c) do {                                        \
        uint32_t dst_ = sbase + (uint32_t)((c) % 3) * STAGE;          \
        CP_ASYNC16(dst_ + sSw,            gXh + (c) * BK);            \
        CP_ASYNC16(dst_ + OFF_ALO + sSw,  gXl + (c) * BK);            \
        CP_ASYNC16(dst_ + OFF_BW  + sSw,  gW  + (c) * BK);            \
        CP_COMMIT();                                                  \
    } while (0)

    LOAD_CHUNK(0);
    LOAD_CHUNK(1);

    for (int kc = 0; kc < NCH; ++kc) {
        if (kc == NCH - 1) { CP_WAIT(0); } else { CP_WAIT(1); }
        __syncthreads();

        if (kc + 2 < NCH) LOAD_CHUNK(kc + 2);

        const uint32_t base = sbase + (uint32_t)(kc % 3) * STAGE;
        #pragma unroll
        for (int ks = 0; ks < 2; ++ks) {
            uint32_t aa[2][4], bb[8][2];
            #pragma unroll
            for (int n2 = 0; n2 < 4; ++n2)
                ldm_x4(bb[2 * n2][0], bb[2 * n2][1], bb[2 * n2 + 1][0],
                       bb[2 * n2 + 1][1], base + OFF_BW + bOff[n2][ks]);
            #pragma unroll
            for (int mi = 0; mi < 2; ++mi)
                ldm_x4(aa[mi][0], aa[mi][1], aa[mi][2], aa[mi][3],
                       base + aPl + aOff[mi][ks]);

            #pragma unroll
            for (int mi = 0; mi < 2; ++mi)
                #pragma unroll
                for (int ni = 0; ni < 8; ++ni)
                    MMA_S8(acc[mi][ni], aa[mi], bb[ni]);
        }
    }
    #undef LOAD_CHUNK

    // ---- quiesce ALL warps' stage reads before overlaying combine bufs ----
    __syncthreads();

    // combine buffer: pos * 8KB inside the dead stage region
    const uint32_t cb = sbase + (uint32_t)pos * 8192;

    if (plane == 1) {
        #pragma unroll
        for (int mi = 0; mi < 2; ++mi)
            #pragma unroll
            for (int ni = 0; ni < 8; ++ni) {
                uint32_t addr = cb + (uint32_t)(((mi * 8 + ni) * 32 + lane) * 16);
                asm volatile("st.shared.v4.b32 [%0], {%1,%2,%3,%4};"
                             :: "r"(addr), "r"((uint32_t)acc[mi][ni][0]),
                                "r"((uint32_t)acc[mi][ni][1]),
                                "r"((uint32_t)acc[mi][ni][2]),
                                "r"((uint32_t)acc[mi][ni][3]) : "memory");
            }
    }
    __syncthreads();

    if (plane == 0) {
        const int dg = lane >> 2;
        const int dt = lane & 3;

        float hv[2][8][4];
        #pragma unroll
        for (int mi = 0; mi < 2; ++mi)
            #pragma unroll
            for (int ni = 0; ni < 8; ++ni) {
                uint32_t lo0, lo1, lo2, lo3;
                uint32_t addr = cb + (uint32_t)(((mi * 8 + ni) * 32 + lane) * 16);
                asm volatile("ld.shared.v4.b32 {%0,%1,%2,%3}, [%4];"
                             : "=r"(lo0), "=r"(lo1), "=r"(lo2), "=r"(lo3)
                             : "r"(addr));
                int aL[4] = {(int)lo0, (int)lo1, (int)lo2, (int)lo3};
                #pragma unroll
                for (int q = 0; q < 4; ++q) {
                    int n = wnn * 64 + ni * 8 + 2 * dt + (q & 1);
                    float hf = fmaf(256.0f, (float)acc[mi][ni][q], (float)aL[q]);
                    float v  = fmaf(hf, INV_S, b1s[n]);
                    hv[mi][ni][q] = fminf(1.0f, fmaxf(-1.0f, v));
                }
            }

        #pragma unroll
        for (int o = 0; o < NOUT; ++o) {
            #pragma unroll
            for (int mi = 0; mi < 2; ++mi) {
                float s0 = 0.0f, s1 = 0.0f;
                #pragma unroll
                for (int ni = 0; ni < 8; ++ni) {
                    int n0 = wnn * 64 + ni * 8 + 2 * dt;
                    float w0 = W2s[o * BN + n0];
                    float w1 = W2s[o * BN + n0 + 1];
                    s0 = fmaf(hv[mi][ni][0], w0, fmaf(hv[mi][ni][1], w1, s0));
                    s1 = fmaf(hv[mi][ni][2], w0, fmaf(hv[mi][ni][3], w1, s1));
                }
                s0 += __shfl_xor_sync(0xffffffffu, s0, 1);
                s0 += __shfl_xor_sync(0xffffffffu, s0, 2);
                s1 += __shfl_xor_sync(0xffffffffu, s1, 1);
                s1 += __shfl_xor_sync(0xffffffffu, s1, 2);
                if (dt == 0) {
                    int r0 = bm + wm * 32 + mi * 16 + dg;
                    atomicAdd(&out[(size_t)r0 * NOUT + o], s0);
                    atomicAdd(&out[(size_t)(r0 + 8) * NOUT + o], s1);
                }
            }
        }
    }
}

// ---------------------------------------------------------------- launch
extern "C" void kernel_launch(void* const* d_in, const int* in_sizes, int n_in,
                              void* d_out, int out_size) {
    const float* X  = (const float*)d_in[0];   // [8192, 784]
    const float* W1 = (const float*)d_in[1];   // [4096, 784]
    const float* b1 = (const float*)d_in[2];   // [4096]
    const float* W2 = (const float*)d_in[3];   // [10, 4096]
    const float* b2 = (const float*)d_in[4];   // [10]
    float* out = (float*)d_out;                // [8192, 10]
    (void)in_sizes; (void)n_in; (void)out_size;

    cudaFuncSetAttribute(fused_i8_kernel,
                         cudaFuncAttributeMaxDynamicSharedMemorySize, SMEM_REQ);

    init_out_kernel<<<(BATCH * NOUT + 255) / 256, 256>>>(out, b2);
    conv_x8_kernel<<<(BATCH * (KP8 / 4) + 255) / 256, 256>>>(X);
    conv_w8_kernel<<<(HID * (KP8 / 4) + 255) / 256, 256>>>(W1);

    dim3 grid(HID / BN, BATCH / BM);   // (32, 64) = 2048 CTAs
    fused_i8_kernel<<<grid, 512, SMEM_REQ>>>(b1, W2, out);
}

// round 15
// speedup vs baseline: 4.3543x; 1.1035x over previous
#include <cuda_runtime.h>
#include <cstdint>

// CovNet_3058016715001 — binarized-weight MLP via int8 mma.sync.
// Round 15: round-14 warp (m32n64 unified acc, plane-specialized, BK=64)
// at 256 threads x 2 CTAs/SM -> two interleaved barrier domains with the
// proven warp shape.
//   h   = clip(x @ sign(W1)^T + b1, -1, 1)     x:[8192,784] W1:[4096,784]
//   out = h @ W2^T + b2                        W2:[10,4096]  out:[8192,10]
//
// x -> Q = round(x*4096) = 256*Qh + Ql (two s8 planes); sign(W1) exact s8.
// h = (256*accH + accL)/4096 + b1 -> clip -> fused fc2 -> atomicAdd.

#define BATCH 8192
#define IN_F  784
#define KP8   832           // 13 * 64
#define HID   4096
#define NOUT  10

#define BM 64
#define BN 128
#define BK 64
#define NCH 13

// stage: A_hi [64x64]=4K | A_lo 4K | B [128x64]=8K
#define OFF_ALO 4096
#define OFF_BW  8192
#define STAGE   16384       // x3 stages = 49152

#define OFF_W2   49152      // [10][128] f32 = 5120
#define OFF_B1   54272      // [128] f32 = 512
#define SMEM_REQ (54784 + 128)

#define SCALE_S 4096.0f
#define INV_S   (1.0f / 4096.0f)

static __device__ char g_Xh8[(size_t)BATCH * KP8];
static __device__ char g_Xl8[(size_t)BATCH * KP8];
static __device__ char g_W8 [(size_t)HID * KP8];

// ---------------------------------------------------------------- helpers
__device__ __forceinline__ uint32_t smem_u32(const void* p) {
    return (uint32_t)__cvta_generic_to_shared(p);
}

#define CP_ASYNC16(s, g) \
    asm volatile("cp.async.cg.shared.global [%0], [%1], 16;" :: "r"(s), "l"(g))
#define CP_COMMIT() asm volatile("cp.async.commit_group;")
#define CP_WAIT(n)  asm volatile("cp.async.wait_group %0;" :: "n"(n) : "memory")

__device__ __forceinline__ void ldm_x4(uint32_t& r0, uint32_t& r1, uint32_t& r2,
                                       uint32_t& r3, uint32_t addr) {
    asm volatile("ldmatrix.sync.aligned.m8n8.x4.shared.b16 {%0,%1,%2,%3}, [%4];"
                 : "=r"(r0), "=r"(r1), "=r"(r2), "=r"(r3) : "r"(addr));
}

#define MMA_S8(d, a, b) \
    asm volatile("mma.sync.aligned.m16n8k32.row.col.s32.s8.s8.s32 " \
        "{%0,%1,%2,%3}, {%4,%5,%6,%7}, {%8,%9}, {%0,%1,%2,%3};" \
        : "+r"((d)[0]), "+r"((d)[1]), "+r"((d)[2]), "+r"((d)[3]) \
        : "r"((a)[0]), "r"((a)[1]), "r"((a)[2]), "r"((a)[3]), \
          "r"((b)[0]), "r"((b)[1]))

__device__ __forceinline__ uint32_t sw128(uint32_t flat) {
    return flat ^ ((flat >> 3) & 0x70);
}

// ---------------------------------------------------------------- prep
__global__ void init_out_kernel(float* __restrict__ out, const float* __restrict__ b2) {
    int i = blockIdx.x * blockDim.x + threadIdx.x;
    if (i < BATCH * NOUT) out[i] = b2[i % NOUT];
}

__global__ void conv_x8_kernel(const float* __restrict__ X) {
    int idx = blockIdx.x * blockDim.x + threadIdx.x;
    if (idx >= BATCH * (KP8 / 4)) return;
    int r  = idx / (KP8 / 4);
    int c4 = (idx % (KP8 / 4)) * 4;
    char hq[4], lq[4];
    #pragma unroll
    for (int j = 0; j < 4; ++j) {
        int col = c4 + j;
        float x = (col < IN_F) ? X[(size_t)r * IN_F + col] : 0.0f;
        int Q = __float2int_rn(x * SCALE_S);
        Q = max(-32512, min(32512, Q));
        int Qh = (Q + 128) >> 8;
        int Ql = Q - (Qh << 8);
        hq[j] = (char)Qh;
        lq[j] = (char)Ql;
    }
    *(char4*)(g_Xh8 + (size_t)r * KP8 + c4) = make_char4(hq[0], hq[1], hq[2], hq[3]);
    *(char4*)(g_Xl8 + (size_t)r * KP8 + c4) = make_char4(lq[0], lq[1], lq[2], lq[3]);
}

__global__ void conv_w8_kernel(const float* __restrict__ W1) {
    int idx = blockIdx.x * blockDim.x + threadIdx.x;
    if (idx >= HID * (KP8 / 4)) return;
    int r  = idx / (KP8 / 4);
    int c4 = (idx % (KP8 / 4)) * 4;
    char s[4];
    #pragma unroll
    for (int j = 0; j < 4; ++j) {
        int col = c4 + j;
        char v = 0;
        if (col < IN_F) {
            float w = W1[(size_t)r * IN_F + col];
            v = (w > 0.0f) ? (char)1 : ((w < 0.0f) ? (char)-1 : (char)0);
        }
        s[j] = v;
    }
    *(char4*)(g_W8 + (size_t)r * KP8 + c4) = make_char4(s[0], s[1], s[2], s[3]);
}

// ---------------------------------------------------------------- main
__global__ void __launch_bounds__(256, 2) fused_i8_kernel(
    const float* __restrict__ b1, const float* __restrict__ W2,
    float* __restrict__ out)
{
    extern __shared__ char smem_raw[];
    const uint32_t rawA  = smem_u32(smem_raw);
    const uint32_t sbase = (rawA + 127) & ~127u;
    char* gbase = smem_raw + (sbase - rawA);
    float* W2s = (float*)(gbase + OFF_W2);   // [10][128]
    float* b1s = (float*)(gbase + OFF_B1);   // [128]

    const int tid   = threadIdx.x;
    const int lane  = tid & 31;
    const int wid   = tid >> 5;
    const int plane = wid & 1;        // 0 = hi, 1 = lo
    const int pos   = wid >> 1;       // 0..3
    const int wm    = pos & 1;        // 2 m-positions (32 rows each)
    const int wnn   = pos >> 1;       // 2 n-positions (64 cols each)

    const int bm = blockIdx.y * BM;
    const int bn = blockIdx.x * BN;

    // ---- stage W2 / b1 slices (epilogue only) ----
    for (int i = tid; i < NOUT * BN; i += 256)
        W2s[i] = W2[(size_t)(i >> 7) * HID + bn + (i & 127)];
    if (tid < BN) b1s[tid] = b1[bn + tid];

    // ---- loader: A planes 1 x 16B / thread, B 2 x 16B / thread ----
    const int lrow = tid >> 2;           // 0..63
    const int lseg = tid & 3;
    const uint32_t aSw  = sw128((uint32_t)tid * 16);
    const uint32_t bSw0 = aSw;
    const uint32_t bSw1 = sw128((uint32_t)tid * 16 + 4096);
    const char* gXh = g_Xh8 + (size_t)(bm + lrow) * KP8 + lseg * 16;
    const char* gXl = g_Xl8 + (size_t)(bm + lrow) * KP8 + lseg * 16;
    const char* gW0 = g_W8  + (size_t)(bn + lrow) * KP8 + lseg * 16;
    const char* gW1 = g_W8  + (size_t)(bn + 64 + lrow) * KP8 + lseg * 16;

    // ---- ldmatrix offsets (64B rows, 2 k-steps) ----
    const int lg  = lane >> 3;
    const int lr8 = lane & 7;
    uint32_t aOff[2][2], bOff[4][2];
    #pragma unroll
    for (int mi = 0; mi < 2; ++mi) {
        int r = wm * 32 + mi * 16 + ((lg & 1) << 3) + lr8;
        #pragma unroll
        for (int ks = 0; ks < 2; ++ks)
            aOff[mi][ks] = sw128((uint32_t)(r * 64 + ks * 32 + (lg >> 1) * 16));
    }
    #pragma unroll
    for (int n2 = 0; n2 < 4; ++n2) {
        int r = wnn * 64 + n2 * 16 + (((lane >> 4) & 1) << 3) + lr8;
        #pragma unroll
        for (int ks = 0; ks < 2; ++ks)
            bOff[n2][ks] = sw128((uint32_t)(r * 64 + ks * 32 + (lg & 1) * 16));
    }

    const uint32_t aPl = plane ? (uint32_t)OFF_ALO : 0u;

    int acc[2][8][4];                 // 64 regs — single plane, n64
    #pragma unroll
    for (int mi = 0; mi < 2; ++mi)
        #pragma unroll
        for (int ni = 0; ni < 8; ++ni)
            #pragma unroll
            for (int q = 0; q < 4; ++q) acc[mi][ni][q] = 0;

    #define LOAD_CHUNK(c) do {                                        \
        uint32_t dst_ = sbase + (uint32_t)((c) % 3) * STAGE;          \
        CP_ASYNC16(dst_ + aSw,            gXh + (c) * BK);            \
        CP_ASYNC16(dst_ + OFF_ALO + aSw,  gXl + (c) * BK);            \
        CP_ASYNC16(dst_ + OFF_BW + bSw0,  gW0 + (c) * BK);            \
        CP_ASYNC16(dst_ + OFF_BW + bSw1,  gW1 + (c) * BK);            \
        CP_COMMIT();                                                  \
    } while (0)

    LOAD_CHUNK(0);
    LOAD_CHUNK(1);

    for (int kc = 0; kc < NCH; ++kc) {
        if (kc == NCH - 1) { CP_WAIT(0); } else { CP_WAIT(1); }
        __syncthreads();

        if (kc + 2 < NCH) LOAD_CHUNK(kc + 2);

        const uint32_t base = sbase + (uint32_t)(kc % 3) * STAGE;
        #pragma unroll
        for (int ks = 0; ks < 2; ++ks) {
            uint32_t aa[2][4], bb[8][2];
            #pragma unroll
            for (int n2 = 0; n2 < 4; ++n2)
                ldm_x4(bb[2 * n2][0], bb[2 * n2][1], bb[2 * n2 + 1][0],
                       bb[2 * n2 + 1][1], base + OFF_BW + bOff[n2][ks]);
            #pragma unroll
            for (int mi = 0; mi < 2; ++mi)
                ldm_x4(aa[mi][0], aa[mi][1], aa[mi][2], aa[mi][3],
                       base + aPl + aOff[mi][ks]);

            #pragma unroll
            for (int mi = 0; mi < 2; ++mi)
                #pragma unroll
                for (int ni = 0; ni < 8; ++ni)
                    MMA_S8(acc[mi][ni], aa[mi], bb[ni]);
        }
    }
    #undef LOAD_CHUNK

    // ---- quiesce ALL warps' stage reads before overlaying combine bufs ----
    __syncthreads();

    // combine buffer: pos * 8KB inside the dead stage region (4 x 8K = 32K)
    const uint32_t cb = sbase + (uint32_t)pos * 8192;

    if (plane == 1) {
        #pragma unroll
        for (int mi = 0; mi < 2; ++mi)
            #pragma unroll
            for (int ni = 0; ni < 8; ++ni) {
                uint32_t addr = cb + (uint32_t)(((mi * 8 + ni) * 32 + lane) * 16);
                asm volatile("st.shared.v4.b32 [%0], {%1,%2,%3,%4};"
                             :: "r"(addr), "r"((uint32_t)acc[mi][ni][0]),
                                "r"((uint32_t)acc[mi][ni][1]),
                                "r"((uint32_t)acc[mi][ni][2]),
                                "r"((uint32_t)acc[mi][ni][3]) : "memory");
            }
    }
    __syncthreads();

    if (plane == 0) {
        const int dg = lane >> 2;
        const int dt = lane & 3;

        float hv[2][8][4];
        #pragma unroll
        for (int mi = 0; mi < 2; ++mi)
            #pragma unroll
            for (int ni = 0; ni < 8; ++ni) {
                uint32_t lo0, lo1, lo2, lo3;
                uint32_t addr = cb + (uint32_t)(((mi * 8 + ni) * 32 + lane) * 16);
                asm volatile("ld.shared.v4.b32 {%0,%1,%2,%3}, [%4];"
                             : "=r"(lo0), "=r"(lo1), "=r"(lo2), "=r"(lo3)
                             : "r"(addr));
                int aL[4] = {(int)lo0, (int)lo1, (int)lo2, (int)lo3};
                #pragma unroll
                for (int q = 0; q < 4; ++q) {
                    int n = wnn * 64 + ni * 8 + 2 * dt + (q & 1);
                    float hf = fmaf(256.0f, (float)acc[mi][ni][q], (float)aL[q]);
                    float v  = fmaf(hf, INV_S, b1s[n]);
                    hv[mi][ni][q] = fminf(1.0f, fmaxf(-1.0f, v));
                }
            }

        #pragma unroll
        for (int o = 0; o < NOUT; ++o) {
            #pragma unroll
            for (int mi = 0; mi < 2; ++mi) {
                float s0 = 0.0f, s1 = 0.0f;
                #pragma unroll
                for (int ni = 0; ni < 8; ++ni) {
                    int n0 = wnn * 64 + ni * 8 + 2 * dt;
                    float w0 = W2s[o * BN + n0];
                    float w1 = W2s[o * BN + n0 + 1];
                    s0 = fmaf(hv[mi][ni][0], w0, fmaf(hv[mi][ni][1], w1, s0));
                    s1 = fmaf(hv[mi][ni][2], w0, fmaf(hv[mi][ni][3], w1, s1));
                }
                s0 += __shfl_xor_sync(0xffffffffu, s0, 1);
                s0 += __shfl_xor_sync(0xffffffffu, s0, 2);
                s1 += __shfl_xor_sync(0xffffffffu, s1, 1);
                s1 += __shfl_xor_sync(0xffffffffu, s1, 2);
                if (dt == 0) {
                    int r0 = bm + wm * 32 + mi * 16 + dg;
                    atomicAdd(&out[(size_t)r0 * NOUT + o], s0);
                    atomicAdd(&out[(size_t)(r0 + 8) * NOUT + o], s1);
                }
            }
        }
    }
}

// ---------------------------------------------------------------- launch
extern "C" void kernel_launch(void* const* d_in, const int* in_sizes, int n_in,
                              void* d_out, int out_size) {
    const float* X  = (const float*)d_in[0];   // [8192, 784]
    const float* W1 = (const float*)d_in[1];   // [4096, 784]
    const float* b1 = (const float*)d_in[2];   // [4096]
    const float* W2 = (const float*)d_in[3];   // [10, 4096]
    const float* b2 = (const float*)d_in[4];   // [10]
    float* out = (float*)d_out;                // [8192, 10]
    (void)in_sizes; (void)n_in; (void)out_size;

    cudaFuncSetAttribute(fused_i8_kernel,
                         cudaFuncAttributeMaxDynamicSharedMemorySize, SMEM_REQ);

    init_out_kernel<<<(BATCH * NOUT + 255) / 256, 256>>>(out, b2);
    conv_x8_kernel<<<(BATCH * (KP8 / 4) + 255) / 256, 256>>>(X);
    conv_w8_kernel<<<(HID * (KP8 / 4) + 255) / 256, 256>>>(W1);

    dim3 grid(HID / BN, BATCH / BM);   // (32, 128) = 4096 CTAs
    fused_i8_kernel<<<grid, 256, SMEM_REQ>>>(b1, W2, out);
}

// round 16
// speedup vs baseline: 4.7828x; 1.0984x over previous
#include <cuda_runtime.h>
#include <cstdint>

// CovNet_3058016715001 — binarized-weight MLP via int8 mma.sync.
// Round 16: round-15 champion (m32n64 plane-specialized warps, 256 thr,
// 2 CTAs/SM) + fully-unrolled 13-chunk k-loop (constant-folded stage
// addressing, cross-chunk scheduling) + 4-stage ring.
//   h   = clip(x @ sign(W1)^T + b1, -1, 1)     x:[8192,784] W1:[4096,784]
//   out = h @ W2^T + b2                        W2:[10,4096]  out:[8192,10]
//
// x -> Q = round(x*4096) = 256*Qh + Ql (two s8 planes); sign(W1) exact s8.
// h = (256*accH + accL)/4096 + b1 -> clip -> fused fc2 -> atomicAdd.

#define BATCH 8192
#define IN_F  784
#define KP8   832           // 13 * 64
#define HID   4096
#define NOUT  10

#define BM 64
#define BN 128
#define BK 64
#define NCH 13

// stage: A_hi [64x64]=4K | A_lo 4K | B [128x64]=8K
#define OFF_ALO 4096
#define OFF_BW  8192
#define STAGE   16384       // x4 stages = 65536

#define OFF_W2   65536      // [10][128] f32 = 5120
#define OFF_B1   70656      // [128] f32 = 512
#define SMEM_REQ (71168 + 128)

#define SCALE_S 4096.0f
#define INV_S   (1.0f / 4096.0f)

static __device__ char g_Xh8[(size_t)BATCH * KP8];
static __device__ char g_Xl8[(size_t)BATCH * KP8];
static __device__ char g_W8 [(size_t)HID * KP8];

// ---------------------------------------------------------------- helpers
__device__ __forceinline__ uint32_t smem_u32(const void* p) {
    return (uint32_t)__cvta_generic_to_shared(p);
}

#define CP_ASYNC16(s, g) \
    asm volatile("cp.async.cg.shared.global [%0], [%1], 16;" :: "r"(s), "l"(g))
#define CP_COMMIT() asm volatile("cp.async.commit_group;")
#define CP_WAIT(n)  asm volatile("cp.async.wait_group %0;" :: "n"(n) : "memory")

__device__ __forceinline__ void ldm_x4(uint32_t& r0, uint32_t& r1, uint32_t& r2,
                                       uint32_t& r3, uint32_t addr) {
    asm volatile("ldmatrix.sync.aligned.m8n8.x4.shared.b16 {%0,%1,%2,%3}, [%4];"
                 : "=r"(r0), "=r"(r1), "=r"(r2), "=r"(r3) : "r"(addr));
}

#define MMA_S8(d, a, b) \
    asm volatile("mma.sync.aligned.m16n8k32.row.col.s32.s8.s8.s32 " \
        "{%0,%1,%2,%3}, {%4,%5,%6,%7}, {%8,%9}, {%0,%1,%2,%3};" \
        : "+r"((d)[0]), "+r"((d)[1]), "+r"((d)[2]), "+r"((d)[3]) \
        : "r"((a)[0]), "r"((a)[1]), "r"((a)[2]), "r"((a)[3]), \
          "r"((b)[0]), "r"((b)[1]))

__device__ __forceinline__ uint32_t sw128(uint32_t flat) {
    return flat ^ ((flat >> 3) & 0x70);
}

// ---------------------------------------------------------------- prep
__global__ void init_out_kernel(float* __restrict__ out, const float* __restrict__ b2) {
    int i = blockIdx.x * blockDim.x + threadIdx.x;
    if (i < BATCH * NOUT) out[i] = b2[i % NOUT];
}

__global__ void conv_x8_kernel(const float* __restrict__ X) {
    int idx = blockIdx.x * blockDim.x + threadIdx.x;
    if (idx >= BATCH * (KP8 / 4)) return;
    int r  = idx / (KP8 / 4);
    int c4 = (idx % (KP8 / 4)) * 4;
    char hq[4], lq[4];
    #pragma unroll
    for (int j = 0; j < 4; ++j) {
        int col = c4 + j;
        float x = (col < IN_F) ? X[(size_t)r * IN_F + col] : 0.0f;
        int Q = __float2int_rn(x * SCALE_S);
        Q = max(-32512, min(32512, Q));
        int Qh = (Q + 128) >> 8;
        int Ql = Q - (Qh << 8);
        hq[j] = (char)Qh;
        lq[j] = (char)Ql;
    }
    *(char4*)(g_Xh8 + (size_t)r * KP8 + c4) = make_char4(hq[0], hq[1], hq[2], hq[3]);
    *(char4*)(g_Xl8 + (size_t)r * KP8 + c4) = make_char4(lq[0], lq[1], lq[2], lq[3]);
}

__global__ void conv_w8_kernel(const float* __restrict__ W1) {
    int idx = blockIdx.x * blockDim.x + threadIdx.x;
    if (idx >= HID * (KP8 / 4)) return;
    int r  = idx / (KP8 / 4);
    int c4 = (idx % (KP8 / 4)) * 4;
    char s[4];
    #pragma unroll
    for (int j = 0; j < 4; ++j) {
        int col = c4 + j;
        char v = 0;
        if (col < IN_F) {
            float w = W1[(size_t)r * IN_F + col];
            v = (w > 0.0f) ? (char)1 : ((w < 0.0f) ? (char)-1 : (char)0);
        }
        s[j] = v;
    }
    *(char4*)(g_W8 + (size_t)r * KP8 + c4) = make_char4(s[0], s[1], s[2], s[3]);
}

// ---------------------------------------------------------------- main
__global__ void __launch_bounds__(256, 2) fused_i8_kernel(
    const float* __restrict__ b1, const float* __restrict__ W2,
    float* __restrict__ out)
{
    extern __shared__ char smem_raw[];
    const uint32_t rawA  = smem_u32(smem_raw);
    const uint32_t sbase = (rawA + 127) & ~127u;
    char* gbase = smem_raw + (sbase - rawA);
    float* W2s = (float*)(gbase + OFF_W2);   // [10][128]
    float* b1s = (float*)(gbase + OFF_B1);   // [128]

    const int tid   = threadIdx.x;
    const int lane  = tid & 31;
    const int wid   = tid >> 5;
    const int plane = wid & 1;        // 0 = hi, 1 = lo
    const int pos   = wid >> 1;       // 0..3
    const int wm    = pos & 1;        // 2 m-positions (32 rows each)
    const int wnn   = pos >> 1;       // 2 n-positions (64 cols each)

    const int bm = blockIdx.y * BM;
    const int bn = blockIdx.x * BN;

    // ---- stage W2 / b1 slices (epilogue only) ----
    for (int i = tid; i < NOUT * BN; i += 256)
        W2s[i] = W2[(size_t)(i >> 7) * HID + bn + (i & 127)];
    if (tid < BN) b1s[tid] = b1[bn + tid];

    // ---- loader: A planes 1 x 16B / thread, B 2 x 16B / thread ----
    const int lrow = tid >> 2;           // 0..63
    const int lseg = tid & 3;
    const uint32_t aSw  = sw128((uint32_t)tid * 16);
    const uint32_t bSw0 = aSw;
    const uint32_t bSw1 = sw128((uint32_t)tid * 16 + 4096);
    const char* gXh = g_Xh8 + (size_t)(bm + lrow) * KP8 + lseg * 16;
    const char* gXl = g_Xl8 + (size_t)(bm + lrow) * KP8 + lseg * 16;
    const char* gW0 = g_W8  + (size_t)(bn + lrow) * KP8 + lseg * 16;
    const char* gW1 = g_W8  + (size_t)(bn + 64 + lrow) * KP8 + lseg * 16;

    // ---- ldmatrix offsets (64B rows, 2 k-steps) ----
    const int lg  = lane >> 3;
    const int lr8 = lane & 7;
    uint32_t aOff[2][2], bOff[4][2];
    #pragma unroll
    for (int mi = 0; mi < 2; ++mi) {
        int r = wm * 32 + mi * 16 + ((lg & 1) << 3) + lr8;
        #pragma unroll
        for (int ks = 0; ks < 2; ++ks)
            aOff[mi][ks] = sw128((uint32_t)(r * 64 + ks * 32 + (lg >> 1) * 16));
    }
    #pragma unroll
    for (int n2 = 0; n2 < 4; ++n2) {
        int r = wnn * 64 + n2 * 16 + (((lane >> 4) & 1) << 3) + lr8;
        #pragma unroll
        for (int ks = 0; ks < 2; ++ks)
            bOff[n2][ks] = sw128((uint32_t)(r * 64 + ks * 32 + (lg & 1) * 16));
    }

    const uint32_t aPl = plane ? (uint32_t)OFF_ALO : 0u;

    int acc[2][8][4];                 // 64 regs — single plane, n64
    #pragma unroll
    for (int mi = 0; mi < 2; ++mi)
        #pragma unroll
        for (int ni = 0; ni < 8; ++ni)
            #pragma unroll
            for (int q = 0; q < 4; ++q) acc[mi][ni][q] = 0;

    #define LOAD_CHUNK(c) do {                                        \
        uint32_t dst_ = sbase + (uint32_t)((c) & 3) * STAGE;          \
        CP_ASYNC16(dst_ + aSw,            gXh + (c) * BK);            \
        CP_ASYNC16(dst_ + OFF_ALO + aSw,  gXl + (c) * BK);            \
        CP_ASYNC16(dst_ + OFF_BW + bSw0,  gW0 + (c) * BK);            \
        CP_ASYNC16(dst_ + OFF_BW + bSw1,  gW1 + (c) * BK);            \
        CP_COMMIT();                                                  \
    } while (0)

    LOAD_CHUNK(0);
    LOAD_CHUNK(1);

    // ---- fully unrolled main loop: constant stage addressing, ptxas can
    //      schedule across chunk boundaries ----
    #pragma unroll
    for (int kc = 0; kc < NCH; ++kc) {
        if (kc == NCH - 1) { CP_WAIT(0); } else { CP_WAIT(1); }
        __syncthreads();

        if (kc + 2 < NCH) LOAD_CHUNK(kc + 2);

        const uint32_t base = sbase + (uint32_t)(kc & 3) * STAGE;
        #pragma unroll
        for (int ks = 0; ks < 2; ++ks) {
            uint32_t aa[2][4], bb[8][2];
            #pragma unroll
            for (int n2 = 0; n2 < 4; ++n2)
                ldm_x4(bb[2 * n2][0], bb[2 * n2][1], bb[2 * n2 + 1][0],
                       bb[2 * n2 + 1][1], base + OFF_BW + bOff[n2][ks]);
            #pragma unroll
            for (int mi = 0; mi < 2; ++mi)
                ldm_x4(aa[mi][0], aa[mi][1], aa[mi][2], aa[mi][3],
                       base + aPl + aOff[mi][ks]);

            #pragma unroll
            for (int mi = 0; mi < 2; ++mi)
                #pragma unroll
                for (int ni = 0; ni < 8; ++ni)
                    MMA_S8(acc[mi][ni], aa[mi], bb[ni]);
        }
    }
    #undef LOAD_CHUNK

    // ---- quiesce ALL warps' stage reads before overlaying combine bufs ----
    __syncthreads();

    // combine buffer: pos * 8KB inside the dead stage region (4 x 8K = 32K)
    const uint32_t cb = sbase + (uint32_t)pos * 8192;

    if (plane == 1) {
        #pragma unroll
        for (int mi = 0; mi < 2; ++mi)
            #pragma unroll
            for (int ni = 0; ni < 8; ++ni) {
                uint32_t addr = cb + (uint32_t)(((mi * 8 + ni) * 32 + lane) * 16);
                asm volatile("st.shared.v4.b32 [%0], {%1,%2,%3,%4};"
                             :: "r"(addr), "r"((uint32_t)acc[mi][ni][0]),
                                "r"((uint32_t)acc[mi][ni][1]),
                                "r"((uint32_t)acc[mi][ni][2]),
                                "r"((uint32_t)acc[mi][ni][3]) : "memory");
            }
    }
    __syncthreads();

    if (plane == 0) {
        const int dg = lane >> 2;
        const int dt = lane & 3;

        float hv[2][8][4];
        #pragma unroll
        for (int mi = 0; mi < 2; ++mi)
            #pragma unroll
            for (int ni = 0; ni < 8; ++ni) {
                uint32_t lo0, lo1, lo2, lo3;
                uint32_t addr = cb + (uint32_t)(((mi * 8 + ni) * 32 + lane) * 16);
                asm volatile("ld.shared.v4.b32 {%0,%1,%2,%3}, [%4];"
                             : "=r"(lo0), "=r"(lo1), "=r"(lo2), "=r"(lo3)
                             : "r"(addr));
                int aL[4] = {(int)lo0, (int)lo1, (int)lo2, (int)lo3};
                #pragma unroll
                for (int q = 0; q < 4; ++q) {
                    int n = wnn * 64 + ni * 8 + 2 * dt + (q & 1);
                    float hf = fmaf(256.0f, (float)acc[mi][ni][q], (float)aL[q]);
                    float v  = fmaf(hf, INV_S, b1s[n]);
                    hv[mi][ni][q] = fminf(1.0f, fmaxf(-1.0f, v));
                }
            }

        #pragma unroll
        for (int o = 0; o < NOUT; ++o) {
            #pragma unroll
            for (int mi = 0; mi < 2; ++mi) {
                float s0 = 0.0f, s1 = 0.0f;
                #pragma unroll
                for (int ni = 0; ni < 8; ++ni) {
                    int n0 = wnn * 64 + ni * 8 + 2 * dt;
                    float w0 = W2s[o * BN + n0];
                    float w1 = W2s[o * BN + n0 + 1];
                    s0 = fmaf(hv[mi][ni][0], w0, fmaf(hv[mi][ni][1], w1, s0));
                    s1 = fmaf(hv[mi][ni][2], w0, fmaf(hv[mi][ni][3], w1, s1));
                }
                s0 += __shfl_xor_sync(0xffffffffu, s0, 1);
                s0 += __shfl_xor_sync(0xffffffffu, s0, 2);
                s1 += __shfl_xor_sync(0xffffffffu, s1, 1);
                s1 += __shfl_xor_sync(0xffffffffu, s1, 2);
                if (dt == 0) {
                    int r0 = bm + wm * 32 + mi * 16 + dg;
                    atomicAdd(&out[(size_t)r0 * NOUT + o], s0);
                    atomicAdd(&out[(size_t)(r0 + 8) * NOUT + o], s1);
                }
            }
        }
    }
}

// ---------------------------------------------------------------- launch
extern "C" void kernel_launch(void* const* d_in, const int* in_sizes, int n_in,
                              void* d_out, int out_size) {
    const float* X  = (const float*)d_in[0];   // [8192, 784]
    const float* W1 = (const float*)d_in[1];   // [4096, 784]
    const float* b1 = (const float*)d_in[2];   // [4096]
    const float* W2 = (const float*)d_in[3];   // [10, 4096]
    const float* b2 = (const float*)d_in[4];   // [10]
    float* out = (float*)d_out;                // [8192, 10]
    (void)in_sizes; (void)n_in; (void)out_size;

    cudaFuncSetAttribute(fused_i8_kernel,
                         cudaFuncAttributeMaxDynamicSharedMemorySize, SMEM_REQ);

    init_out_kernel<<<(BATCH * NOUT + 255) / 256, 256>>>(out, b2);
    conv_x8_kernel<<<(BATCH * (KP8 / 4) + 255) / 256, 256>>>(X);
    conv_w8_kernel<<<(HID * (KP8 / 4) + 255) / 256, 256>>>(W1);

    dim3 grid(HID / BN, BATCH / BM);   // (32, 128) = 4096 CTAs
    fused_i8_kernel<<<grid, 256, SMEM_REQ>>>(b1, W2, out);
}